// round 1
// baseline (speedup 1.0000x reference)
#include <cuda_runtime.h>

// Problem constants
// B=16, Wn=64, K=256, E=128, O=64
// inputs: x(16,64,256), lin_w(128,128), lin_b(128), a(128), bias_kk(256,256),
//         fc_w(64,256), fc_b(64); output (16,64,64) fp32

// Scratch (device globals; no allocation allowed)
__device__ float g_L[16 * 256 * 128];   // L'[b,k,e] = v@W1 + lin_b
__device__ float g_R[16 * 256 * 128];   // R [b,k,e] = v@W2
__device__ float g_sL[16 * 256];        // 0.2 * sum_e a_e * L'
__device__ float g_sR[16 * 256];        // 0.2 * sum_e a_e * R
__device__ float g_h[16 * 256 * 64];    // sigmoid(attn @ v)

// ---------------------------------------------------------------------------
// k1: L'[b,k,e] = sum_w x[b,w,k] * lin_w[e, half*64 + w]  (+ lin_b for half 0)
// grid = 16 b * 16 ktiles * 2 halves = 512 blocks, 256 threads
// ---------------------------------------------------------------------------
__global__ void __launch_bounds__(256, 4)
k1_lr(const float* __restrict__ x, const float* __restrict__ lin_w,
      const float* __restrict__ lin_b) {
    __shared__ float wsT[64 * 128];   // wsT[w][e] for this half
    __shared__ float xs[16 * 65];     // xs[kk][w] = x[b, w, k0+kk]
    __shared__ float lbs[128];

    int bx = blockIdx.x;
    int b = bx >> 5;
    int rem = bx & 31;
    int kt = rem >> 1;
    int half = rem & 1;
    int k0 = kt * 16;
    int tid = threadIdx.x;
    int mloc = tid & 127;             // output column e
    int wh = tid >> 7;                // 0/1

    // load weights transposed: wsT[w*128 + e] = lin_w[e*128 + half*64 + w]
    const float4* g4 =
        reinterpret_cast<const float4*>(lin_w + mloc * 128 + half * 64 + wh * 32);
#pragma unroll
    for (int i = 0; i < 8; i++) {
        float4 v = g4[i];
        int w = wh * 32 + i * 4;
        wsT[(w + 0) * 128 + mloc] = v.x;
        wsT[(w + 1) * 128 + mloc] = v.y;
        wsT[(w + 2) * 128 + mloc] = v.z;
        wsT[(w + 3) * 128 + mloc] = v.w;
    }
    // load x tile (transposed view v[b,k,w] = x[b,w,k])
#pragma unroll
    for (int t = 0; t < 4; t++) {
        int idx = t * 256 + tid;
        int kk = idx & 15, w = idx >> 4;
        xs[kk * 65 + w] = x[b * 16384 + w * 256 + k0 + kk];
    }
    if (tid < 128) lbs[tid] = lin_b[tid];
    __syncthreads();

    int kg = wh;  // thread handles 8 k rows: kg*8 .. kg*8+7
    float acc[8];
#pragma unroll
    for (int r = 0; r < 8; r++) acc[r] = 0.f;

#pragma unroll 8
    for (int w = 0; w < 64; w++) {
        float wv = wsT[w * 128 + mloc];
#pragma unroll
        for (int r = 0; r < 8; r++)
            acc[r] = fmaf(xs[(kg * 8 + r) * 65 + w], wv, acc[r]);
    }

    float bias = (half == 0) ? lbs[mloc] : 0.f;
    float* outp = (half == 0) ? g_L : g_R;
#pragma unroll
    for (int r = 0; r < 8; r++) {
        int kk = kg * 8 + r;
        outp[(b * 256 + k0 + kk) * 128 + mloc] = acc[r] + bias;
    }
}

// ---------------------------------------------------------------------------
// k1b: sL[row] = 0.2 * sum_e a_e * L'[row,e];  sR likewise.
// grid = 4096 rows, 128 threads
// ---------------------------------------------------------------------------
__global__ void __launch_bounds__(128, 8)
k1b_s(const float* __restrict__ a) {
    int row = blockIdx.x;
    int tid = threadIdx.x;
    float av = a[tid];
    float vl = av * g_L[row * 128 + tid];
    float vr = av * g_R[row * 128 + tid];
#pragma unroll
    for (int o = 16; o > 0; o >>= 1) {
        vl += __shfl_xor_sync(0xffffffffu, vl, o);
        vr += __shfl_xor_sync(0xffffffffu, vr, o);
    }
    __shared__ float rb[8];
    int wid = tid >> 5;
    if ((tid & 31) == 0) { rb[wid] = vl; rb[4 + wid] = vr; }
    __syncthreads();
    if (tid == 0) {
        g_sL[row] = 0.2f * (rb[0] + rb[1] + rb[2] + rb[3]);
        g_sR[row] = 0.2f * (rb[4] + rb[5] + rb[6] + rb[7]);
    }
}

// ---------------------------------------------------------------------------
// k2: fused  e = 0.8*sum a*relu(L_i + R_j) + sL_i + sR_j + bias_kk
//            p = softmax_j(e)
//            h[b,i,w] = sigmoid( sum_j p * x[b,w,j] )
// grid = 16 b * 16 itiles = 256 blocks (TI=16), 128 threads, TJ=32 (8 j-tiles)
// shared: 42.9 KB static
// ---------------------------------------------------------------------------
__global__ void __launch_bounds__(128, 2)
k2_attn(const float* __restrict__ x, const float* __restrict__ bias_kk,
        const float* __restrict__ a) {
    // float offsets into S
    const int LS = 0;            // 16 x 129
    const int RS = 2064;         // 32 x 129 (reused as hred 4x16x64 later)
    const int ES = 6192;         // 16 x 257
    const int A8 = 10304;        // 128
    const int SRS = 10432;       // 256
    const int SLS = 10688;       // 16
    const int INV = 10704;       // 16
    __shared__ float S[10720];

    int tid = threadIdx.x;
    int b = blockIdx.x >> 4;
    int i0 = (blockIdx.x & 15) << 4;

    // ---- Phase A: load L tile, a, sL, sR ----
    const float* Lg = g_L + (b * 256 + i0) * 128;
#pragma unroll
    for (int t = 0; t < 16; t++) {
        int idx = t * 128 + tid;
        int ii = idx >> 7, e = idx & 127;
        S[LS + ii * 129 + e] = Lg[idx];
    }
    S[A8 + tid] = 0.8f * a[tid];
    S[SRS + tid] = g_sR[b * 256 + tid];
    S[SRS + 128 + tid] = g_sR[b * 256 + 128 + tid];
    if (tid < 16) S[SLS + tid] = g_sL[b * 256 + i0 + tid];

    int tii = tid >> 4;    // 0..7  -> ii in {tii, tii+8}
    int tjj = tid & 15;    // 0..15 -> jj in {tjj, tjj+16}

    // ---- Phase B: e-scores over 8 j-tiles of 32 ----
    for (int jt = 0; jt < 8; jt++) {
        __syncthreads();
        // load R tile (scalar, conflict-free)
        const float* Rg = g_R + (b * 256 + jt * 32) * 128;
#pragma unroll
        for (int t = 0; t < 32; t++) {
            int idx = t * 128 + tid;
            int jj = idx >> 7, e = idx & 127;
            S[RS + jj * 129 + e] = Rg[idx];
        }
        __syncthreads();

        float a00 = 0.f, a01 = 0.f, a10 = 0.f, a11 = 0.f;
        const float* Lp0 = &S[LS + tii * 129];
        const float* Lp1 = &S[LS + (tii + 8) * 129];
        const float* Rp0 = &S[RS + tjj * 129];
        const float* Rp1 = &S[RS + (tjj + 16) * 129];
        const float* Ap = &S[A8];
#pragma unroll 8
        for (int e = 0; e < 128; e++) {
            float av = Ap[e];
            float l0 = Lp0[e], l1 = Lp1[e];
            float r0 = Rp0[e], r1 = Rp1[e];
            a00 = fmaf(av, fmaxf(l0 + r0, 0.f), a00);
            a01 = fmaf(av, fmaxf(l0 + r1, 0.f), a01);
            a10 = fmaf(av, fmaxf(l1 + r0, 0.f), a10);
            a11 = fmaf(av, fmaxf(l1 + r1, 0.f), a11);
        }
        int j0 = jt * 32 + tjj, j1 = j0 + 16;
        int gi0 = (i0 + tii) * 256, gi1 = (i0 + tii + 8) * 256;
        S[ES + tii * 257 + j0] = a00 + S[SLS + tii] + S[SRS + j0] + bias_kk[gi0 + j0];
        S[ES + tii * 257 + j1] = a01 + S[SLS + tii] + S[SRS + j1] + bias_kk[gi0 + j1];
        S[ES + (tii + 8) * 257 + j0] = a10 + S[SLS + tii + 8] + S[SRS + j0] + bias_kk[gi1 + j0];
        S[ES + (tii + 8) * 257 + j1] = a11 + S[SLS + tii + 8] + S[SRS + j1] + bias_kk[gi1 + j1];
    }
    __syncthreads();

    // ---- softmax over j (rows of 256); 4 warps x 4 rows ----
    int wid = tid >> 5, lane = tid & 31;
#pragma unroll
    for (int s = 0; s < 4; s++) {
        int r = wid + s * 4;
        float v[8];
        float m = -1e30f;
#pragma unroll
        for (int u = 0; u < 8; u++) {
            v[u] = S[ES + r * 257 + u * 32 + lane];
            m = fmaxf(m, v[u]);
        }
#pragma unroll
        for (int o = 16; o > 0; o >>= 1) m = fmaxf(m, __shfl_xor_sync(0xffffffffu, m, o));
        float sum = 0.f;
#pragma unroll
        for (int u = 0; u < 8; u++) {
            float p = __expf(v[u] - m);
            S[ES + r * 257 + u * 32 + lane] = p;
            sum += p;
        }
#pragma unroll
        for (int o = 16; o > 0; o >>= 1) sum += __shfl_xor_sync(0xffffffffu, sum, o);
        if (lane == 0) S[INV + r] = 1.f / sum;
    }
    __syncthreads();

    // ---- h phase: h[b,i,w] = sigmoid(inv_i * sum_j p_ij * x[b,w,j]) ----
    int w2 = tid & 31, q = tid >> 5;   // w in {w2, w2+32}, j in [q*64, q*64+64)
    float f0[16], f1[16];
#pragma unroll
    for (int ii = 0; ii < 16; ii++) { f0[ii] = 0.f; f1[ii] = 0.f; }
    const float* xp0 = x + b * 16384 + w2 * 256;
    const float* xp1 = xp0 + 32 * 256;
    for (int j4 = q * 64; j4 < q * 64 + 64; j4 += 4) {
        float4 xv0 = *reinterpret_cast<const float4*>(xp0 + j4);
        float4 xv1 = *reinterpret_cast<const float4*>(xp1 + j4);
#pragma unroll
        for (int ii = 0; ii < 16; ii++) {
            const float* pp = &S[ES + ii * 257 + j4];
            float p0 = pp[0], p1 = pp[1], p2 = pp[2], p3 = pp[3];
            f0[ii] += xv0.x * p0 + xv0.y * p1 + xv0.z * p2 + xv0.w * p3;
            f1[ii] += xv1.x * p0 + xv1.y * p1 + xv1.z * p2 + xv1.w * p3;
        }
    }
    // partial sums into (reused) RS region: hred[q][ii][w]
#pragma unroll
    for (int ii = 0; ii < 16; ii++) {
        S[RS + (q * 16 + ii) * 64 + w2] = f0[ii];
        S[RS + (q * 16 + ii) * 64 + w2 + 32] = f1[ii];
    }
    __syncthreads();
#pragma unroll
    for (int t = 0; t < 8; t++) {
        int idx = t * 128 + tid;
        int ii = idx >> 6, w = idx & 63;
        float sum = S[RS + (0 * 16 + ii) * 64 + w] + S[RS + (1 * 16 + ii) * 64 + w] +
                    S[RS + (2 * 16 + ii) * 64 + w] + S[RS + (3 * 16 + ii) * 64 + w];
        float val = sum * S[INV + ii];
        g_h[(b * 256 + i0 + ii) * 64 + w] = 1.f / (1.f + __expf(-val));
    }
}

// ---------------------------------------------------------------------------
// k3: out[b,w,o] = sum_k h[b,k,w] * fc_w[o,k] + fc_b[o]
// grid = 16 b * 8 wtiles * 2 ohalves = 256 blocks, 256 threads
// ---------------------------------------------------------------------------
__global__ void __launch_bounds__(256, 4)
k3_fc(const float* __restrict__ fc_w, const float* __restrict__ fc_b,
      float* __restrict__ out) {
    __shared__ float fwsT[256 * 32];  // fwsT[k][ol]
    __shared__ float hs[256 * 8];     // hs[k][ww]

    int bx = blockIdx.x;
    int b = bx >> 4;
    int rem = bx & 15;
    int wt = rem >> 1;
    int oh = rem & 1;
    int w0 = wt * 8, o0 = oh * 32;
    int tid = threadIdx.x;
    int ol = tid & 31, kg = tid >> 5;

    const float4* fg4 =
        reinterpret_cast<const float4*>(fc_w + (o0 + ol) * 256 + kg * 32);
#pragma unroll
    for (int i = 0; i < 8; i++) {
        float4 v = fg4[i];
        int k = kg * 32 + i * 4;
        fwsT[(k + 0) * 32 + ol] = v.x;
        fwsT[(k + 1) * 32 + ol] = v.y;
        fwsT[(k + 2) * 32 + ol] = v.z;
        fwsT[(k + 3) * 32 + ol] = v.w;
    }
#pragma unroll
    for (int t = 0; t < 8; t++) {
        int idx = t * 256 + tid;
        int k = idx >> 3, ww = idx & 7;
        hs[idx] = g_h[(b * 256 + k) * 64 + w0 + ww];
    }
    __syncthreads();

    int ww = kg;  // 0..7
    float acc = 0.f;
#pragma unroll 8
    for (int k = 0; k < 256; k++)
        acc = fmaf(hs[k * 8 + ww], fwsT[k * 32 + ol], acc);

    out[(b * 64 + w0 + ww) * 64 + o0 + ol] = acc + __ldg(&fc_b[o0 + ol]);
}

// ---------------------------------------------------------------------------
extern "C" void kernel_launch(void* const* d_in, const int* in_sizes, int n_in,
                              void* d_out, int out_size) {
    const float* x       = (const float*)d_in[0];
    const float* lin_w   = (const float*)d_in[1];
    const float* lin_b   = (const float*)d_in[2];
    const float* a       = (const float*)d_in[3];
    const float* bias_kk = (const float*)d_in[4];
    const float* fc_w    = (const float*)d_in[5];
    const float* fc_b    = (const float*)d_in[6];
    float* out = (float*)d_out;

    k1_lr<<<512, 256>>>(x, lin_w, lin_b);
    k1b_s<<<4096, 128>>>(a);
    k2_attn<<<256, 128>>>(x, bias_kk, a);
    k3_fc<<<256, 256>>>(fc_w, fc_b, out);
}

// round 2
// speedup vs baseline: 1.1707x; 1.1707x over previous
#include <cuda_runtime.h>

// B=16, Wn=64, K=256, E=128, O=64
// x(16,64,256), lin_w(128,128), lin_b(128), a(128), bias_kk(256,256),
// fc_w(64,256), fc_b(64) -> out(16,64,64) fp32

typedef unsigned long long ull;

__device__ __forceinline__ ull f2_add(ull a, ull b) {
    ull r; asm("add.rn.f32x2 %0,%1,%2;" : "=l"(r) : "l"(a), "l"(b)); return r;
}
__device__ __forceinline__ ull f2_fma(ull a, ull b, ull c) {
    ull r; asm("fma.rn.f32x2 %0,%1,%2,%3;" : "=l"(r) : "l"(a), "l"(b), "l"(c)); return r;
}
__device__ __forceinline__ float f2_hadd(ull a) {
    float lo, hi; asm("mov.b64 {%0,%1},%2;" : "=f"(lo), "=f"(hi) : "l"(a)); return lo + hi;
}

// Scratch (device globals)
__device__ float g_L[16 * 256 * 128];   // L'[b,k,e] = v@W1 + lin_b
__device__ float g_R[16 * 256 * 128];   // R [b,k,e] = v@W2
__device__ float g_sL[16 * 256];        // 0.6 * sum_e a_e * L'
__device__ float g_sR[16 * 256];        // 0.6 * sum_e a_e * R
__device__ float g_h[16 * 256 * 64];    // sigmoid(attn @ v)

// ---------------------------------------------------------------------------
// k1: L'/R projection + fused row-dot (sL/sR).
// grid = 16 b * 16 ktiles * 2 halves = 512 blocks, 256 threads
// ---------------------------------------------------------------------------
__global__ void __launch_bounds__(256, 4)
k1_lr(const float* __restrict__ x, const float* __restrict__ lin_w,
      const float* __restrict__ lin_b, const float* __restrict__ a) {
    __shared__ float ws[128 * 66];   // ws[e][w]
    __shared__ float xs[16 * 66];    // xs[kk][w]
    __shared__ float part[2 * 4 * 8];

    int bx = blockIdx.x;
    int b = bx >> 5;
    int rem = bx & 31;
    int kt = rem >> 1;
    int half = rem & 1;
    int k0 = kt * 16;
    int tid = threadIdx.x;
    int mloc = tid & 127;   // e
    int wh = tid >> 7;      // k-row group (0/1)

    // stage weights transposed into [e][w] (w contiguous for packed reads)
    {
        const float4* g4 =
            reinterpret_cast<const float4*>(lin_w + mloc * 128 + half * 64 + wh * 32);
        float* dst = &ws[mloc * 66 + wh * 32];
#pragma unroll
        for (int i = 0; i < 8; i++) {
            float4 v = g4[i];
            float2* d2 = reinterpret_cast<float2*>(dst + i * 4);
            d2[0] = make_float2(v.x, v.y);
            d2[1] = make_float2(v.z, v.w);
        }
    }
#pragma unroll
    for (int t = 0; t < 4; t++) {
        int idx = t * 256 + tid;
        int kk = idx & 15, w = idx >> 4;
        xs[kk * 66 + w] = x[b * 16384 + w * 256 + k0 + kk];
    }
    __syncthreads();

    ull acc[8];
#pragma unroll
    for (int r = 0; r < 8; r++) acc[r] = 0ULL;

    const ull* wsp = reinterpret_cast<const ull*>(&ws[mloc * 66]);
    const float* xbase = &xs[wh * 8 * 66];
#pragma unroll 4
    for (int wp = 0; wp < 32; wp++) {
        ull wv = wsp[wp];
#pragma unroll
        for (int r = 0; r < 8; r++)
            acc[r] = f2_fma(*reinterpret_cast<const ull*>(xbase + r * 66 + wp * 2),
                            wv, acc[r]);
    }

    float av = a[mloc];
    float fb = (half == 0) ? lin_b[mloc] : 0.f;
    float* outp = (half == 0) ? g_L : g_R;
    float pr[8];
#pragma unroll
    for (int r = 0; r < 8; r++) {
        float f = f2_hadd(acc[r]) + fb;
        outp[(b * 256 + k0 + wh * 8 + r) * 128 + mloc] = f;
        pr[r] = av * f;
    }
    // reduce pr over e (128 threads with same wh)
#pragma unroll
    for (int o = 16; o > 0; o >>= 1) {
#pragma unroll
        for (int r = 0; r < 8; r++)
            pr[r] += __shfl_xor_sync(0xffffffffu, pr[r], o);
    }
    int lane = tid & 31, w4 = (tid >> 5) & 3;
    if (lane == 0) {
#pragma unroll
        for (int r = 0; r < 8; r++) part[(wh * 4 + w4) * 8 + r] = pr[r];
    }
    __syncthreads();
    if (tid < 16) {
        int h2 = tid >> 3, r = tid & 7;
        float s = part[(h2 * 4 + 0) * 8 + r] + part[(h2 * 4 + 1) * 8 + r] +
                  part[(h2 * 4 + 2) * 8 + r] + part[(h2 * 4 + 3) * 8 + r];
        float* sp = (half == 0) ? g_sL : g_sR;
        sp[b * 256 + k0 + h2 * 8 + r] = 0.6f * s;
    }
}

// ---------------------------------------------------------------------------
// k2: e = sL_i + sR_j + sum_e (0.4 a_e)|L'+R| + bias_kk ; softmax over j;
//     h = sigmoid(attn @ v). grid = 256 blocks (16b x 16 itiles), 128 thr.
// ---------------------------------------------------------------------------
__global__ void __launch_bounds__(128, 2)
k2_attn(const float* __restrict__ x, const float* __restrict__ bias_kk,
        const float* __restrict__ a) {
    const int LS = 0;            // 16 x 130
    const int RS = 2080;         // 32 x 130 (reused as hred [4][16][64])
    const int ES = 6240;         // 16 x 260
    const int CS = 10400;        // 128 (0.4*a)
    const int SRS = 10528;       // 256
    const int SLS = 10784;       // 16
    const int INV = 10800;       // 16
    __shared__ float S[10816];
    const ull ABSM = 0x7FFFFFFF7FFFFFFFULL;

    int tid = threadIdx.x;
    int b = blockIdx.x >> 4;
    int i0 = (blockIdx.x & 15) << 4;

    // stage L tile
    const float* Lg = g_L + (b * 256 + i0) * 128;
#pragma unroll
    for (int t = 0; t < 4; t++) {
        int idx = t * 128 + tid;          // 512 float4
        int row = idx >> 5, c4 = idx & 31;
        float4 v = *reinterpret_cast<const float4*>(Lg + row * 128 + c4 * 4);
        float2* d = reinterpret_cast<float2*>(&S[LS + row * 130 + c4 * 4]);
        d[0] = make_float2(v.x, v.y);
        d[1] = make_float2(v.z, v.w);
    }
    S[CS + tid] = 0.4f * a[tid];
    S[SRS + tid] = g_sR[b * 256 + tid];
    S[SRS + 128 + tid] = g_sR[b * 256 + 128 + tid];
    if (tid < 16) S[SLS + tid] = g_sL[b * 256 + i0 + tid];

    int tii = tid >> 4;   // 0..7 -> rows {tii, tii+8}
    int tjj = tid & 15;   // 0..15 -> cols {tjj, tjj+16}
    const ull* Lp0 = reinterpret_cast<const ull*>(&S[LS + tii * 130]);
    const ull* Lp1 = reinterpret_cast<const ull*>(&S[LS + (tii + 8) * 130]);
    const ull* Cp  = reinterpret_cast<const ull*>(&S[CS]);

    for (int jt = 0; jt < 8; jt++) {
        __syncthreads();
        const float* Rg = g_R + (b * 256 + jt * 32) * 128;
#pragma unroll
        for (int t = 0; t < 8; t++) {
            int idx = t * 128 + tid;      // 1024 float4
            int row = idx >> 5, c4 = idx & 31;
            float4 v = *reinterpret_cast<const float4*>(Rg + row * 128 + c4 * 4);
            float2* d = reinterpret_cast<float2*>(&S[RS + row * 130 + c4 * 4]);
            d[0] = make_float2(v.x, v.y);
            d[1] = make_float2(v.z, v.w);
        }
        __syncthreads();

        const ull* Rp0 = reinterpret_cast<const ull*>(&S[RS + tjj * 130]);
        const ull* Rp1 = reinterpret_cast<const ull*>(&S[RS + (tjj + 16) * 130]);
        ull a00 = 0, a01 = 0, a10 = 0, a11 = 0;
#pragma unroll 8
        for (int ep = 0; ep < 64; ep++) {
            ull c = Cp[ep];
            ull l0 = Lp0[ep], l1 = Lp1[ep];
            ull r0 = Rp0[ep], r1 = Rp1[ep];
            a00 = f2_fma(f2_add(l0, r0) & ABSM, c, a00);
            a01 = f2_fma(f2_add(l0, r1) & ABSM, c, a01);
            a10 = f2_fma(f2_add(l1, r0) & ABSM, c, a10);
            a11 = f2_fma(f2_add(l1, r1) & ABSM, c, a11);
        }
        int j0 = jt * 32 + tjj, j1 = j0 + 16;
        int gi0 = (i0 + tii) * 256, gi1 = (i0 + tii + 8) * 256;
        float sl0 = S[SLS + tii], sl1 = S[SLS + tii + 8];
        S[ES + tii * 260 + j0]       = f2_hadd(a00) + sl0 + S[SRS + j0] + bias_kk[gi0 + j0];
        S[ES + tii * 260 + j1]       = f2_hadd(a01) + sl0 + S[SRS + j1] + bias_kk[gi0 + j1];
        S[ES + (tii + 8) * 260 + j0] = f2_hadd(a10) + sl1 + S[SRS + j0] + bias_kk[gi1 + j0];
        S[ES + (tii + 8) * 260 + j1] = f2_hadd(a11) + sl1 + S[SRS + j1] + bias_kk[gi1 + j1];
    }
    __syncthreads();

    // softmax over j
    int wid = tid >> 5, lane = tid & 31;
#pragma unroll
    for (int s = 0; s < 4; s++) {
        int r = wid + s * 4;
        float v[8];
        float m = -1e30f;
#pragma unroll
        for (int u = 0; u < 8; u++) {
            v[u] = S[ES + r * 260 + u * 32 + lane];
            m = fmaxf(m, v[u]);
        }
#pragma unroll
        for (int o = 16; o > 0; o >>= 1) m = fmaxf(m, __shfl_xor_sync(0xffffffffu, m, o));
        float sum = 0.f;
#pragma unroll
        for (int u = 0; u < 8; u++) {
            float p = __expf(v[u] - m);
            S[ES + r * 260 + u * 32 + lane] = p;
            sum += p;
        }
#pragma unroll
        for (int o = 16; o > 0; o >>= 1) sum += __shfl_xor_sync(0xffffffffu, sum, o);
        if (lane == 0) S[INV + r] = 1.f / sum;
    }
    __syncthreads();

    // h phase: packed over j pairs
    int w2 = tid & 31, q = tid >> 5;
    ull f0[16], f1[16];
#pragma unroll
    for (int ii = 0; ii < 16; ii++) { f0[ii] = 0ULL; f1[ii] = 0ULL; }
    const float* xp0 = x + b * 16384 + w2 * 256;
    const float* xp1 = xp0 + 32 * 256;
    for (int j4 = q * 64; j4 < q * 64 + 64; j4 += 4) {
        ulonglong2 xq0 = *reinterpret_cast<const ulonglong2*>(xp0 + j4);
        ulonglong2 xq1 = *reinterpret_cast<const ulonglong2*>(xp1 + j4);
#pragma unroll
        for (int ii = 0; ii < 16; ii++) {
            ulonglong2 pq = *reinterpret_cast<const ulonglong2*>(&S[ES + ii * 260 + j4]);
            f0[ii] = f2_fma(xq0.x, pq.x, f0[ii]);
            f0[ii] = f2_fma(xq0.y, pq.y, f0[ii]);
            f1[ii] = f2_fma(xq1.x, pq.x, f1[ii]);
            f1[ii] = f2_fma(xq1.y, pq.y, f1[ii]);
        }
    }
#pragma unroll
    for (int ii = 0; ii < 16; ii++) {
        S[RS + (q * 16 + ii) * 64 + w2]      = f2_hadd(f0[ii]);
        S[RS + (q * 16 + ii) * 64 + w2 + 32] = f2_hadd(f1[ii]);
    }
    __syncthreads();
#pragma unroll
    for (int t = 0; t < 8; t++) {
        int idx = t * 128 + tid;
        int ii = idx >> 6, w = idx & 63;
        float sum = S[RS + ii * 64 + w] + S[RS + (16 + ii) * 64 + w] +
                    S[RS + (32 + ii) * 64 + w] + S[RS + (48 + ii) * 64 + w];
        float val = sum * S[INV + ii];
        g_h[(b * 256 + i0 + ii) * 64 + w] = 1.f / (1.f + __expf(-val));
    }
}

// ---------------------------------------------------------------------------
// k3: out[b,w,o] = sum_k h[b,k,w] * fc_w[o,k] + fc_b[o]
// grid = 16 b * 4 wtiles = 64 blocks, 256 threads, packed over k pairs
// ---------------------------------------------------------------------------
__global__ void __launch_bounds__(256, 2)
k3_fc(const float* __restrict__ fc_w, const float* __restrict__ fc_b,
      float* __restrict__ out) {
    __shared__ float hsT[16 * 130];   // hsT[w][k] for current k-chunk
    __shared__ float fws[64 * 130];   // fws[o][k]

    int bx = blockIdx.x;
    int b = bx >> 2, wq = bx & 3;
    int w0 = wq * 16;
    int tid = threadIdx.x;
    int w16 = tid & 15, og = tid >> 4;

    ull acc[4] = {0ULL, 0ULL, 0ULL, 0ULL};
    for (int kc = 0; kc < 2; kc++) {
        int k0c = kc * 128;
        __syncthreads();
#pragma unroll
        for (int t = 0; t < 8; t++) {
            int idx = t * 256 + tid;
            int kk = idx >> 4, ww = idx & 15;
            hsT[ww * 130 + kk] = g_h[(b * 256 + k0c + kk) * 64 + w0 + ww];
        }
#pragma unroll
        for (int t = 0; t < 8; t++) {
            int idx = t * 256 + tid;       // 2048 float4
            int row = idx >> 5, c4 = idx & 31;
            float4 v = *reinterpret_cast<const float4*>(fc_w + row * 256 + k0c + c4 * 4);
            float2* d = reinterpret_cast<float2*>(&fws[row * 130 + c4 * 4]);
            d[0] = make_float2(v.x, v.y);
            d[1] = make_float2(v.z, v.w);
        }
        __syncthreads();

        const ull* hp = reinterpret_cast<const ull*>(&hsT[w16 * 130]);
#pragma unroll 8
        for (int kp = 0; kp < 64; kp++) {
            ull h2 = hp[kp];
#pragma unroll
            for (int m = 0; m < 4; m++)
                acc[m] = f2_fma(h2,
                    *reinterpret_cast<const ull*>(&fws[(og + 16 * m) * 130 + kp * 2]),
                    acc[m]);
        }
    }
#pragma unroll
    for (int m = 0; m < 4; m++) {
        int o = og + 16 * m;
        out[(b * 64 + w0 + w16) * 64 + o] = f2_hadd(acc[m]) + fc_b[o];
    }
}

// ---------------------------------------------------------------------------
extern "C" void kernel_launch(void* const* d_in, const int* in_sizes, int n_in,
                              void* d_out, int out_size) {
    const float* x       = (const float*)d_in[0];
    const float* lin_w   = (const float*)d_in[1];
    const float* lin_b   = (const float*)d_in[2];
    const float* a       = (const float*)d_in[3];
    const float* bias_kk = (const float*)d_in[4];
    const float* fc_w    = (const float*)d_in[5];
    const float* fc_b    = (const float*)d_in[6];
    float* out = (float*)d_out;

    k1_lr<<<512, 256>>>(x, lin_w, lin_b, a);
    k2_attn<<<256, 128>>>(x, bias_kk, a);
    k3_fc<<<64, 256>>>(fc_w, fc_b, out);
}